// round 1
// baseline (speedup 1.0000x reference)
#include <cuda_runtime.h>
#include <math.h>

// Problem constants
#define BB    1024
#define LL    1024
#define NCAT  20
#define NNUM  10
#define EE    32
#define HH    256
#define TOPK  30

// Device scratch (no allocations allowed)
__device__ float g_fused[BB * 128];   // [tgt_e | interest | cat_pool | num_e]
__device__ float g_qk[BB * EE];       // tgt_e @ (Wq Wk^T) / sqrt(128)
__device__ float g_Wqk[EE * EE];
__device__ float g_Wvo[EE * EE];

// ---------------------------------------------------------------------------
// Precompute fused 32x32 matrices: Wqk = Wq @ Wk^T * (1/sqrt(128)), Wvo = Wv @ Wo
// ---------------------------------------------------------------------------
__global__ void precompute_kernel(const float* __restrict__ Wq,
                                  const float* __restrict__ Wk,
                                  const float* __restrict__ Wv,
                                  const float* __restrict__ Wo) {
    int tid = threadIdx.x;          // 1024 threads
    int e1 = tid >> 5, e2 = tid & 31;
    float s1 = 0.f, s2 = 0.f;
#pragma unroll 8
    for (int a = 0; a < 128; a++) {
        s1 += Wq[e1 * 128 + a] * Wk[e2 * 128 + a];
        s2 += Wv[e1 * 128 + a] * Wo[a * 32 + e2];
    }
    g_Wqk[e1 * 32 + e2] = s1 * 0.08838834764831845f;  // 1/sqrt(128)
    g_Wvo[e1 * 32 + e2] = s2;
}

// ---------------------------------------------------------------------------
// Front kernel: per-batch-row. tgt gather, cat_pool, num_e, qk vector.
// ---------------------------------------------------------------------------
__global__ void front_kernel(const int* __restrict__ cats,
                             const float* __restrict__ nums,
                             const int* __restrict__ tgt_ids,
                             const float* __restrict__ cat_emb,
                             const float* __restrict__ Wnum,
                             const float* __restrict__ bnum,
                             const float* __restrict__ Wpool,
                             const float* __restrict__ bpool) {
    int b = blockIdx.x;
    int tid = threadIdx.x;          // 128 threads
    __shared__ float s_cat[NCAT * EE];  // 640
    __shared__ float s_tgt[EE];
    __shared__ float s_part[4][EE];

    for (int i = tid; i < NCAT * EE; i += 128)
        s_cat[i] = cat_emb[(long)cats[b * NCAT + (i >> 5)] * EE + (i & 31)];
    if (tid < EE)
        s_tgt[tid] = cat_emb[(long)tgt_ids[b] * EE + tid];
    __syncthreads();

    int e = tid & 31, p = tid >> 5;
    float acc = 0.f;
    for (int i = p * 160; i < (p + 1) * 160; i++)
        acc += s_cat[i] * Wpool[i * EE + e];
    s_part[p][e] = acc;
    __syncthreads();

    if (tid < EE) {
        float cp = bpool[e] + s_part[0][e] + s_part[1][e] + s_part[2][e] + s_part[3][e];
        float ne = bnum[e];
#pragma unroll
        for (int j = 0; j < NNUM; j++) ne += nums[b * NNUM + j] * Wnum[j * EE + e];
        float qk = 0.f;
#pragma unroll
        for (int e2 = 0; e2 < EE; e2++) qk += s_tgt[e2] * g_Wqk[e2 * EE + e];
        float* fr = g_fused + (long)b * 128;
        fr[e]       = s_tgt[e];
        fr[64 + e]  = cp;
        fr[96 + e]  = ne;
        g_qk[b * EE + e] = qk;
    }
}

// ---------------------------------------------------------------------------
// Attention kernel: per-batch-row. scores -> top-30 -> softmax -> pooled -> Wvo.
// ---------------------------------------------------------------------------
__global__ void attn_kernel(const int* __restrict__ seqs,
                            const float* __restrict__ seq_emb,
                            const float* __restrict__ bo) {
    int b = blockIdx.x;
    int tid = threadIdx.x;          // 256 threads
    __shared__ float s_scores[LL];
    __shared__ float s_qk[EE];
    __shared__ float s_val[TOPK];
    __shared__ int   s_idx[TOPK];
    __shared__ float s_w[TOPK];
    __shared__ float s_pool[EE];
    __shared__ float redv[8];
    __shared__ int   redi[8];

    if (tid < EE) s_qk[tid] = g_qk[b * EE + tid];
    __syncthreads();

    const int* srow = seqs + (long)b * LL;
    // scores[l] = qk . seq_emb[srow[l]]  (scale already folded into Wqk)
    for (int l = tid; l < LL; l += 256) {
        const float4* er = reinterpret_cast<const float4*>(seq_emb + (long)srow[l] * EE);
        float s = 0.f;
#pragma unroll
        for (int c = 0; c < 8; c++) {
            float4 v = er[c];
            s += s_qk[c * 4 + 0] * v.x + s_qk[c * 4 + 1] * v.y +
                 s_qk[c * 4 + 2] * v.z + s_qk[c * 4 + 3] * v.w;
        }
        s_scores[l] = s;
    }
    __syncthreads();

    // iterative top-30 (values sorted descending by construction)
    for (int k = 0; k < TOPK; k++) {
        float m = -INFINITY; int mi = 0;
        for (int l = tid; l < LL; l += 256) {
            float v = s_scores[l];
            if (v > m) { m = v; mi = l; }
        }
#pragma unroll
        for (int off = 16; off; off >>= 1) {
            float om = __shfl_down_sync(0xffffffffu, m, off);
            int   oi = __shfl_down_sync(0xffffffffu, mi, off);
            if (om > m) { m = om; mi = oi; }
        }
        if ((tid & 31) == 0) { redv[tid >> 5] = m; redi[tid >> 5] = mi; }
        __syncthreads();
        if (tid == 0) {
            float bm = redv[0]; int bi = redi[0];
#pragma unroll
            for (int w = 1; w < 8; w++)
                if (redv[w] > bm) { bm = redv[w]; bi = redi[w]; }
            s_val[k] = bm; s_idx[k] = bi;
            s_scores[bi] = -INFINITY;
        }
        __syncthreads();
    }

    // softmax over the 30 selected values
    if (tid == 0) {
        float mx = s_val[0];
        float sum = 0.f;
#pragma unroll
        for (int k = 0; k < TOPK; k++) { float e_ = expf(s_val[k] - mx); s_w[k] = e_; sum += e_; }
        float inv = 1.f / sum;
#pragma unroll
        for (int k = 0; k < TOPK; k++) s_w[k] *= inv;
    }
    __syncthreads();

    // pooled[e] = sum_k w_k * seq_emb[idx_k][e]
    if (tid < EE) {
        float p = 0.f;
#pragma unroll
        for (int k = 0; k < TOPK; k++)
            p += s_w[k] * seq_emb[(long)srow[s_idx[k]] * EE + tid];
        s_pool[tid] = p;
    }
    __syncthreads();

    // interest = pooled @ Wvo + bo  -> fused[32:64]
    if (tid < EE) {
        float acc = bo[tid];
#pragma unroll
        for (int e = 0; e < EE; e++) acc += s_pool[e] * g_Wvo[e * EE + tid];
        g_fused[(long)b * 128 + EE + tid] = acc;
    }
}

// ---------------------------------------------------------------------------
// MLP tail: 8 batch rows per block, 256 threads (one output column each).
// h = relu(fused @ Wmlp + bmlp); h = qnn(h) twice; out = h @ Wout + bout.
// ---------------------------------------------------------------------------
#define ROWS 8
__global__ void mlp_kernel(const float* __restrict__ Wmlp, const float* __restrict__ bmlp,
                           const float* __restrict__ W11, const float* __restrict__ b11,
                           const float* __restrict__ W12, const float* __restrict__ b12,
                           const float* __restrict__ W1p, const float* __restrict__ b1p,
                           const float* __restrict__ W21, const float* __restrict__ b21,
                           const float* __restrict__ W22, const float* __restrict__ b22,
                           const float* __restrict__ W2p, const float* __restrict__ b2p,
                           const float* __restrict__ Wout, const float* __restrict__ bout,
                           float* __restrict__ out) {
    int b0 = blockIdx.x * ROWS;
    int j = threadIdx.x;            // 256 threads = output column
    __shared__ float s_f[ROWS][128];
    __shared__ float s_h[ROWS][HH];
    __shared__ float s_q[ROWS][HH];

    for (int i = j; i < ROWS * 128; i += 256)
        s_f[i >> 7][i & 127] = g_fused[(long)b0 * 128 + i];
    __syncthreads();

    // h = relu(fused @ Wmlp + bmlp)
    {
        float acc[ROWS];
#pragma unroll
        for (int r = 0; r < ROWS; r++) acc[r] = bmlp[j];
#pragma unroll 4
        for (int i = 0; i < 128; i++) {
            float w = Wmlp[i * HH + j];
#pragma unroll
            for (int r = 0; r < ROWS; r++) acc[r] += s_f[r][i] * w;
        }
#pragma unroll
        for (int r = 0; r < ROWS; r++) s_h[r][j] = fmaxf(acc[r], 0.f);
    }
    __syncthreads();

    const float* Ws1[2] = { W11, W21 };  const float* Bs1[2] = { b11, b21 };
    const float* Ws2[2] = { W12, W22 };  const float* Bs2[2] = { b12, b22 };
    const float* Wsp[2] = { W1p, W2p };  const float* Bsp[2] = { b1p, b2p };

    for (int blk = 0; blk < 2; blk++) {
        const float* Wa = Ws1[blk]; const float* Wb = Ws2[blk];
        float a1[ROWS], a2[ROWS];
        float bb1 = Bs1[blk][j], bb2 = Bs2[blk][j];
#pragma unroll
        for (int r = 0; r < ROWS; r++) { a1[r] = bb1; a2[r] = bb2; }
#pragma unroll 4
        for (int i = 0; i < HH; i++) {
            float w1 = Wa[i * HH + j];
            float w2 = Wb[i * HH + j];
#pragma unroll
            for (int r = 0; r < ROWS; r++) {
                float hv = s_h[r][i];
                a1[r] += hv * w1;
                a2[r] += hv * w2;
            }
        }
#pragma unroll
        for (int r = 0; r < ROWS; r++) s_q[r][j] = a1[r] * a2[r];
        __syncthreads();

        const float* Wp = Wsp[blk];
        float ap[ROWS];
        float bbp = Bsp[blk][j];
#pragma unroll
        for (int r = 0; r < ROWS; r++) ap[r] = bbp;
#pragma unroll 4
        for (int i = 0; i < HH; i++) {
            float wp = Wp[i * HH + j];
#pragma unroll
            for (int r = 0; r < ROWS; r++) ap[r] += s_q[r][i] * wp;
        }
        __syncthreads();
#pragma unroll
        for (int r = 0; r < ROWS; r++) s_h[r][j] = s_h[r][j] + ap[r];
        __syncthreads();
    }

    // out[b0+w] = sum_j h[w][j]*Wout[j] + bout  (warp w reduces row w)
    {
        int w = j >> 5, lane = j & 31;
        float v = 0.f;
#pragma unroll
        for (int c = lane; c < HH; c += 32) v += s_h[w][c] * Wout[c];
#pragma unroll
        for (int off = 16; off; off >>= 1) v += __shfl_down_sync(0xffffffffu, v, off);
        if (lane == 0) out[b0 + w] = v + bout[0];
    }
}

// ---------------------------------------------------------------------------
extern "C" void kernel_launch(void* const* d_in, const int* in_sizes, int n_in,
                              void* d_out, int out_size) {
    const int*   cats    = (const int*)  d_in[0];
    const float* nums    = (const float*)d_in[1];
    const int*   seqs    = (const int*)  d_in[2];
    const int*   tgt_ids = (const int*)  d_in[3];
    const float* cat_emb = (const float*)d_in[4];
    const float* seq_emb = (const float*)d_in[5];
    const float* Wnum    = (const float*)d_in[6];
    const float* bnum    = (const float*)d_in[7];
    const float* Wq      = (const float*)d_in[8];
    const float* Wk      = (const float*)d_in[9];
    const float* Wv      = (const float*)d_in[10];
    const float* Wo      = (const float*)d_in[11];
    const float* bo      = (const float*)d_in[12];
    const float* Wpool   = (const float*)d_in[13];
    const float* bpool   = (const float*)d_in[14];
    const float* Wmlp    = (const float*)d_in[15];
    const float* bmlp    = (const float*)d_in[16];
    const float* q1_W1   = (const float*)d_in[17];
    const float* q1_b1   = (const float*)d_in[18];
    const float* q1_W2   = (const float*)d_in[19];
    const float* q1_b2   = (const float*)d_in[20];
    const float* q1_Wp   = (const float*)d_in[21];
    const float* q1_bp   = (const float*)d_in[22];
    const float* q2_W1   = (const float*)d_in[23];
    const float* q2_b1   = (const float*)d_in[24];
    const float* q2_W2   = (const float*)d_in[25];
    const float* q2_b2   = (const float*)d_in[26];
    const float* q2_Wp   = (const float*)d_in[27];
    const float* q2_bp   = (const float*)d_in[28];
    const float* Wout    = (const float*)d_in[29];
    const float* bout    = (const float*)d_in[30];
    float* out = (float*)d_out;

    precompute_kernel<<<1, 1024>>>(Wq, Wk, Wv, Wo);
    front_kernel<<<BB, 128>>>(cats, nums, tgt_ids, cat_emb, Wnum, bnum, Wpool, bpool);
    attn_kernel<<<BB, 256>>>(seqs, seq_emb, bo);
    mlp_kernel<<<BB / ROWS, 256>>>(Wmlp, bmlp,
                                   q1_W1, q1_b1, q1_W2, q1_b2, q1_Wp, q1_bp,
                                   q2_W1, q2_b1, q2_W2, q2_b2, q2_Wp, q2_bp,
                                   Wout, bout, out);
}

// round 2
// speedup vs baseline: 1.2551x; 1.2551x over previous
#include <cuda_runtime.h>
#include <cuda_pipeline.h>
#include <math.h>

// Problem constants
#define BB    1024
#define LL    1024
#define NCAT  20
#define NNUM  10
#define EE    32
#define HH    256
#define TOPK  30
#define ROWS  8

// Device scratch (no allocations allowed)
__device__ float g_fused[BB * 128];   // [tgt_e | interest | cat_pool | num_e]
__device__ float g_qk[BB * EE];       // tgt_e @ (Wq Wk^T) / sqrt(128)
__device__ float g_Wqk[EE * EE];
__device__ float g_Wvo[EE * EE];

// ---------------------------------------------------------------------------
// Precompute fused 32x32 matrices: Wqk = Wq @ Wk^T * (1/sqrt(128)), Wvo = Wv @ Wo
// ---------------------------------------------------------------------------
__global__ void precompute_kernel(const float* __restrict__ Wq,
                                  const float* __restrict__ Wk,
                                  const float* __restrict__ Wv,
                                  const float* __restrict__ Wo) {
    int tid = threadIdx.x;          // 1024 threads
    int e1 = tid >> 5, e2 = tid & 31;
    float s1 = 0.f, s2 = 0.f;
#pragma unroll 8
    for (int a = 0; a < 128; a++) {
        s1 += Wq[e1 * 128 + a] * Wk[e2 * 128 + a];
        s2 += Wv[e1 * 128 + a] * Wo[a * 32 + e2];
    }
    g_Wqk[e1 * 32 + e2] = s1 * 0.08838834764831845f;  // 1/sqrt(128)
    g_Wvo[e1 * 32 + e2] = s2;
}

// ---------------------------------------------------------------------------
// Front kernel: per-batch-row. tgt gather, cat_pool, num_e, qk vector.
// ---------------------------------------------------------------------------
__global__ void front_kernel(const int* __restrict__ cats,
                             const float* __restrict__ nums,
                             const int* __restrict__ tgt_ids,
                             const float* __restrict__ cat_emb,
                             const float* __restrict__ Wnum,
                             const float* __restrict__ bnum,
                             const float* __restrict__ Wpool,
                             const float* __restrict__ bpool) {
    int b = blockIdx.x;
    int tid = threadIdx.x;          // 128 threads
    __shared__ float s_cat[NCAT * EE];  // 640
    __shared__ float s_tgt[EE];
    __shared__ float s_part[4][EE];

    for (int i = tid; i < NCAT * EE; i += 128)
        s_cat[i] = cat_emb[(long)cats[b * NCAT + (i >> 5)] * EE + (i & 31)];
    if (tid < EE)
        s_tgt[tid] = cat_emb[(long)tgt_ids[b] * EE + tid];
    __syncthreads();

    int e = tid & 31, p = tid >> 5;
    float acc = 0.f;
    for (int i = p * 160; i < (p + 1) * 160; i++)
        acc += s_cat[i] * Wpool[i * EE + e];
    s_part[p][e] = acc;
    __syncthreads();

    if (tid < EE) {
        float cp = bpool[e] + s_part[0][e] + s_part[1][e] + s_part[2][e] + s_part[3][e];
        float ne = bnum[e];
#pragma unroll
        for (int j = 0; j < NNUM; j++) ne += nums[b * NNUM + j] * Wnum[j * EE + e];
        float qk = 0.f;
#pragma unroll
        for (int e2 = 0; e2 < EE; e2++) qk += s_tgt[e2] * g_Wqk[e2 * EE + e];
        float* fr = g_fused + (long)b * 128;
        fr[e]       = s_tgt[e];
        fr[64 + e]  = cp;
        fr[96 + e]  = ne;
        g_qk[b * EE + e] = qk;
    }
}

// ---------------------------------------------------------------------------
// Attention kernel: per-batch-row. scores -> top-30 -> softmax -> pooled -> Wvo.
// ---------------------------------------------------------------------------
__global__ void attn_kernel(const int* __restrict__ seqs,
                            const float* __restrict__ seq_emb,
                            const float* __restrict__ bo) {
    int b = blockIdx.x;
    int tid = threadIdx.x;          // 256 threads
    __shared__ float s_scores[LL];
    __shared__ float s_qk[EE];
    __shared__ float s_val[TOPK];
    __shared__ int   s_idx[TOPK];
    __shared__ float s_w[TOPK];
    __shared__ float s_pool[EE];
    __shared__ float redv[8];
    __shared__ int   redi[8];

    if (tid < EE) s_qk[tid] = g_qk[b * EE + tid];
    __syncthreads();

    const int* srow = seqs + (long)b * LL;
    for (int l = tid; l < LL; l += 256) {
        const float4* er = reinterpret_cast<const float4*>(seq_emb + (long)srow[l] * EE);
        float s = 0.f;
#pragma unroll
        for (int c = 0; c < 8; c++) {
            float4 v = er[c];
            s += s_qk[c * 4 + 0] * v.x + s_qk[c * 4 + 1] * v.y +
                 s_qk[c * 4 + 2] * v.z + s_qk[c * 4 + 3] * v.w;
        }
        s_scores[l] = s;
    }
    __syncthreads();

    // iterative top-30
    for (int k = 0; k < TOPK; k++) {
        float m = -INFINITY; int mi = 0;
        for (int l = tid; l < LL; l += 256) {
            float v = s_scores[l];
            if (v > m) { m = v; mi = l; }
        }
#pragma unroll
        for (int off = 16; off; off >>= 1) {
            float om = __shfl_down_sync(0xffffffffu, m, off);
            int   oi = __shfl_down_sync(0xffffffffu, mi, off);
            if (om > m) { m = om; mi = oi; }
        }
        if ((tid & 31) == 0) { redv[tid >> 5] = m; redi[tid >> 5] = mi; }
        __syncthreads();
        if (tid == 0) {
            float bm = redv[0]; int bi = redi[0];
#pragma unroll
            for (int w = 1; w < 8; w++)
                if (redv[w] > bm) { bm = redv[w]; bi = redi[w]; }
            s_val[k] = bm; s_idx[k] = bi;
            s_scores[bi] = -INFINITY;
        }
        __syncthreads();
    }

    if (tid == 0) {
        float mx = s_val[0];
        float sum = 0.f;
#pragma unroll
        for (int k = 0; k < TOPK; k++) { float e_ = expf(s_val[k] - mx); s_w[k] = e_; sum += e_; }
        float inv = 1.f / sum;
#pragma unroll
        for (int k = 0; k < TOPK; k++) s_w[k] *= inv;
    }
    __syncthreads();

    if (tid < EE) {
        float p = 0.f;
#pragma unroll
        for (int k = 0; k < TOPK; k++)
            p += s_w[k] * seq_emb[(long)srow[s_idx[k]] * EE + tid];
        s_pool[tid] = p;
    }
    __syncthreads();

    if (tid < EE) {
        float acc = bo[tid];
#pragma unroll
        for (int e = 0; e < EE; e++) acc += s_pool[e] * g_Wvo[e * EE + tid];
        g_fused[(long)b * 128 + EE + tid] = acc;
    }
}

// ---------------------------------------------------------------------------
// MLP tail with cp.async double-buffered weight staging.
//   smem layout (floats): s_f[ROWS*128] | s_h[ROWS*256] | s_q[ROWS*256] |
//                         wbuf[2 * 16384]   (stage = 16384 floats = 64KB)
// ---------------------------------------------------------------------------
#define STAGE_F 16384

// Single-matrix GEMM stage: acc[r] += sum_i s_x[r][i] * W[i][j]
template<int K, int KT>
__device__ __forceinline__ void gemm_single(const float* __restrict__ W,
                                            const float* s_x, int xstride,
                                            float* wbuf, int j, float acc[ROWS]) {
    constexpr int T = K / KT;
    constexpr int F4 = KT * 256 / 4;     // float4 copies per tile
    // prefetch tile 0
    for (int u = threadIdx.x; u < F4; u += 256)
        __pipeline_memcpy_async(&wbuf[u * 4], &W[u * 4], 16);
    __pipeline_commit();
#pragma unroll
    for (int t = 0; t < T; t++) {
        if (t + 1 < T) {
            const float* src = W + (t + 1) * KT * 256;
            float* dst = wbuf + ((t + 1) & 1) * STAGE_F;
            for (int u = threadIdx.x; u < F4; u += 256)
                __pipeline_memcpy_async(&dst[u * 4], &src[u * 4], 16);
            __pipeline_commit();
            __pipeline_wait_prior(1);
        } else {
            __pipeline_wait_prior(0);
        }
        __syncthreads();
        const float* bw = wbuf + (t & 1) * STAGE_F;
#pragma unroll 2
        for (int i0 = 0; i0 < KT; i0 += 4) {
            float4 hv[ROWS];
#pragma unroll
            for (int r = 0; r < ROWS; r++)
                hv[r] = *(const float4*)&s_x[r * xstride + t * KT + i0];
#pragma unroll
            for (int ii = 0; ii < 4; ii++) {
                float w = bw[(i0 + ii) * 256 + j];
#pragma unroll
                for (int r = 0; r < ROWS; r++) {
                    float h = ii == 0 ? hv[r].x : ii == 1 ? hv[r].y : ii == 2 ? hv[r].z : hv[r].w;
                    acc[r] += h * w;
                }
            }
        }
        __syncthreads();
    }
}

// Dual-matrix GEMM stage (qnn W1/W2): a1 += s_x@Wa, a2 += s_x@Wb. K=256, KT=32.
__device__ __forceinline__ void gemm_dual(const float* __restrict__ Wa,
                                          const float* __restrict__ Wb,
                                          const float* s_x,
                                          float* wbuf, int j,
                                          float a1[ROWS], float a2[ROWS]) {
    constexpr int KT = 32, T = 8;
    constexpr int F4 = KT * 256 / 4;     // 2048 float4 per matrix per tile
    for (int u = threadIdx.x; u < F4; u += 256) {
        __pipeline_memcpy_async(&wbuf[u * 4], &Wa[u * 4], 16);
        __pipeline_memcpy_async(&wbuf[8192 + u * 4], &Wb[u * 4], 16);
    }
    __pipeline_commit();
#pragma unroll
    for (int t = 0; t < T; t++) {
        if (t + 1 < T) {
            const float* sa = Wa + (t + 1) * KT * 256;
            const float* sb = Wb + (t + 1) * KT * 256;
            float* dst = wbuf + ((t + 1) & 1) * STAGE_F;
            for (int u = threadIdx.x; u < F4; u += 256) {
                __pipeline_memcpy_async(&dst[u * 4], &sa[u * 4], 16);
                __pipeline_memcpy_async(&dst[8192 + u * 4], &sb[u * 4], 16);
            }
            __pipeline_commit();
            __pipeline_wait_prior(1);
        } else {
            __pipeline_wait_prior(0);
        }
        __syncthreads();
        const float* bwa = wbuf + (t & 1) * STAGE_F;
        const float* bwb = bwa + 8192;
#pragma unroll 2
        for (int i0 = 0; i0 < KT; i0 += 4) {
            float4 hv[ROWS];
#pragma unroll
            for (int r = 0; r < ROWS; r++)
                hv[r] = *(const float4*)&s_x[r * 256 + t * KT + i0];
#pragma unroll
            for (int ii = 0; ii < 4; ii++) {
                float w1 = bwa[(i0 + ii) * 256 + j];
                float w2 = bwb[(i0 + ii) * 256 + j];
#pragma unroll
                for (int r = 0; r < ROWS; r++) {
                    float h = ii == 0 ? hv[r].x : ii == 1 ? hv[r].y : ii == 2 ? hv[r].z : hv[r].w;
                    a1[r] += h * w1;
                    a2[r] += h * w2;
                }
            }
        }
        __syncthreads();
    }
}

__global__ __launch_bounds__(256)
void mlp_kernel(const float* __restrict__ Wmlp, const float* __restrict__ bmlp,
                const float* __restrict__ W11, const float* __restrict__ b11,
                const float* __restrict__ W12, const float* __restrict__ b12,
                const float* __restrict__ W1p, const float* __restrict__ b1p,
                const float* __restrict__ W21, const float* __restrict__ b21,
                const float* __restrict__ W22, const float* __restrict__ b22,
                const float* __restrict__ W2p, const float* __restrict__ b2p,
                const float* __restrict__ Wout, const float* __restrict__ bout,
                float* __restrict__ out) {
    extern __shared__ float smem[];
    float* s_f = smem;                 // ROWS*128 = 1024
    float* s_h = smem + 1024;          // ROWS*256 = 2048
    float* s_q = s_h + 2048;           // 2048
    float* wbuf = s_q + 2048;          // 2*16384

    int b0 = blockIdx.x * ROWS;
    int j = threadIdx.x;

    for (int i = j; i < ROWS * 128; i += 256)
        s_f[i] = g_fused[(long)b0 * 128 + i];
    __syncthreads();

    // h = relu(fused @ Wmlp + bmlp)
    {
        float acc[ROWS];
        float bb = bmlp[j];
#pragma unroll
        for (int r = 0; r < ROWS; r++) acc[r] = bb;
        gemm_single<128, 64>(Wmlp, s_f, 128, wbuf, j, acc);
#pragma unroll
        for (int r = 0; r < ROWS; r++) s_h[r * 256 + j] = fmaxf(acc[r], 0.f);
    }
    // note: next gemm's internal __syncthreads (post-prefetch) publishes s_h

    const float* Ws1[2] = { W11, W21 };  const float* Bs1[2] = { b11, b21 };
    const float* Ws2[2] = { W12, W22 };  const float* Bs2[2] = { b12, b22 };
    const float* Wsp[2] = { W1p, W2p };  const float* Bsp[2] = { b1p, b2p };

#pragma unroll
    for (int blk = 0; blk < 2; blk++) {
        float a1[ROWS], a2[ROWS];
        float bb1 = Bs1[blk][j], bb2 = Bs2[blk][j];
#pragma unroll
        for (int r = 0; r < ROWS; r++) { a1[r] = bb1; a2[r] = bb2; }
        gemm_dual(Ws1[blk], Ws2[blk], s_h, wbuf, j, a1, a2);
#pragma unroll
        for (int r = 0; r < ROWS; r++) s_q[r * 256 + j] = a1[r] * a2[r];

        float ap[ROWS];
        float bbp = Bsp[blk][j];
#pragma unroll
        for (int r = 0; r < ROWS; r++) ap[r] = bbp;
        gemm_single<256, 64>(Wsp[blk], s_q, 256, wbuf, j, ap);
#pragma unroll
        for (int r = 0; r < ROWS; r++) s_h[r * 256 + j] = s_h[r * 256 + j] + ap[r];
        __syncthreads();
    }

    // out[b0+w] = sum_j h[w][j]*Wout[j] + bout
    {
        int w = j >> 5, lane = j & 31;
        float v = 0.f;
#pragma unroll
        for (int c = lane; c < HH; c += 32) v += s_h[w * 256 + c] * Wout[c];
#pragma unroll
        for (int off = 16; off; off >>= 1) v += __shfl_down_sync(0xffffffffu, v, off);
        if (lane == 0) out[b0 + w] = v + bout[0];
    }
}

// ---------------------------------------------------------------------------
extern "C" void kernel_launch(void* const* d_in, const int* in_sizes, int n_in,
                              void* d_out, int out_size) {
    const int*   cats    = (const int*)  d_in[0];
    const float* nums    = (const float*)d_in[1];
    const int*   seqs    = (const int*)  d_in[2];
    const int*   tgt_ids = (const int*)  d_in[3];
    const float* cat_emb = (const float*)d_in[4];
    const float* seq_emb = (const float*)d_in[5];
    const float* Wnum    = (const float*)d_in[6];
    const float* bnum    = (const float*)d_in[7];
    const float* Wq      = (const float*)d_in[8];
    const float* Wk      = (const float*)d_in[9];
    const float* Wv      = (const float*)d_in[10];
    const float* Wo      = (const float*)d_in[11];
    const float* bo      = (const float*)d_in[12];
    const float* Wpool   = (const float*)d_in[13];
    const float* bpool   = (const float*)d_in[14];
    const float* Wmlp    = (const float*)d_in[15];
    const float* bmlp    = (const float*)d_in[16];
    const float* q1_W1   = (const float*)d_in[17];
    const float* q1_b1   = (const float*)d_in[18];
    const float* q1_W2   = (const float*)d_in[19];
    const float* q1_b2   = (const float*)d_in[20];
    const float* q1_Wp   = (const float*)d_in[21];
    const float* q1_bp   = (const float*)d_in[22];
    const float* q2_W1   = (const float*)d_in[23];
    const float* q2_b1   = (const float*)d_in[24];
    const float* q2_W2   = (const float*)d_in[25];
    const float* q2_b2   = (const float*)d_in[26];
    const float* q2_Wp   = (const float*)d_in[27];
    const float* q2_bp   = (const float*)d_in[28];
    const float* Wout    = (const float*)d_in[29];
    const float* bout    = (const float*)d_in[30];
    float* out = (float*)d_out;

    static bool attr_set = false;
    if (!attr_set) {
        cudaFuncSetAttribute(mlp_kernel, cudaFuncAttributeMaxDynamicSharedMemorySize,
                             (1024 + 2048 + 2048 + 2 * STAGE_F) * sizeof(float));
        attr_set = true;
    }

    precompute_kernel<<<1, 1024>>>(Wq, Wk, Wv, Wo);
    front_kernel<<<BB, 128>>>(cats, nums, tgt_ids, cat_emb, Wnum, bnum, Wpool, bpool);
    attn_kernel<<<BB, 256>>>(seqs, seq_emb, bo);
    mlp_kernel<<<BB / ROWS, 256, (1024 + 2048 + 2048 + 2 * STAGE_F) * sizeof(float)>>>(
        Wmlp, bmlp,
        q1_W1, q1_b1, q1_W2, q1_b2, q1_Wp, q1_bp,
        q2_W1, q2_b1, q2_W2, q2_b2, q2_Wp, q2_bp,
        Wout, bout, out);
}

// round 3
// speedup vs baseline: 1.3241x; 1.0550x over previous
#include <cuda_runtime.h>
#include <cuda_pipeline.h>
#include <math.h>

// Problem constants
#define BB    1024
#define LL    1024
#define NCAT  20
#define NNUM  10
#define EE    32
#define HH    256
#define TOPK  30
#define ROWS  8

// Device scratch (no allocations allowed)
__device__ float g_fused[BB * 128];   // [tgt_e | interest | cat_pool | num_e]
__device__ float g_qk[BB * EE];       // tgt_e @ (Wq Wk^T) / sqrt(128)
__device__ float g_Wqk[EE * EE];
__device__ float g_Wvo[EE * EE];

// ---------------------------------------------------------------------------
// Precompute fused 32x32 matrices: Wqk = Wq @ Wk^T * (1/sqrt(128)), Wvo = Wv @ Wo
// ---------------------------------------------------------------------------
__global__ void precompute_kernel(const float* __restrict__ Wq,
                                  const float* __restrict__ Wk,
                                  const float* __restrict__ Wv,
                                  const float* __restrict__ Wo) {
    int tid = threadIdx.x;          // 1024 threads
    int e1 = tid >> 5, e2 = tid & 31;
    float s1 = 0.f, s2 = 0.f;
#pragma unroll 8
    for (int a = 0; a < 128; a++) {
        s1 += Wq[e1 * 128 + a] * Wk[e2 * 128 + a];
        s2 += Wv[e1 * 128 + a] * Wo[a * 32 + e2];
    }
    g_Wqk[e1 * 32 + e2] = s1 * 0.08838834764831845f;  // 1/sqrt(128)
    g_Wvo[e1 * 32 + e2] = s2;
}

// ---------------------------------------------------------------------------
// Front kernel: per-batch-row. tgt gather, cat_pool, num_e, qk vector.
// ---------------------------------------------------------------------------
__global__ void front_kernel(const int* __restrict__ cats,
                             const float* __restrict__ nums,
                             const int* __restrict__ tgt_ids,
                             const float* __restrict__ cat_emb,
                             const float* __restrict__ Wnum,
                             const float* __restrict__ bnum,
                             const float* __restrict__ Wpool,
                             const float* __restrict__ bpool) {
    int b = blockIdx.x;
    int tid = threadIdx.x;          // 128 threads
    __shared__ float s_cat[NCAT * EE];  // 640
    __shared__ float s_tgt[EE];
    __shared__ float s_part[4][EE];

    for (int i = tid; i < NCAT * EE; i += 128)
        s_cat[i] = cat_emb[(long)cats[b * NCAT + (i >> 5)] * EE + (i & 31)];
    if (tid < EE)
        s_tgt[tid] = cat_emb[(long)tgt_ids[b] * EE + tid];
    __syncthreads();

    int e = tid & 31, p = tid >> 5;
    float acc = 0.f;
#pragma unroll 4
    for (int i = p * 160; i < (p + 1) * 160; i++)
        acc += s_cat[i] * Wpool[i * EE + e];
    s_part[p][e] = acc;
    __syncthreads();

    if (tid < EE) {
        float cp = bpool[e] + s_part[0][e] + s_part[1][e] + s_part[2][e] + s_part[3][e];
        float ne = bnum[e];
#pragma unroll
        for (int j = 0; j < NNUM; j++) ne += nums[b * NNUM + j] * Wnum[j * EE + e];
        float qk = 0.f;
#pragma unroll
        for (int e2 = 0; e2 < EE; e2++) qk += s_tgt[e2] * g_Wqk[e2 * EE + e];
        float* fr = g_fused + (long)b * 128;
        fr[e]       = s_tgt[e];
        fr[64 + e]  = cp;
        fr[96 + e]  = ne;
        g_qk[b * EE + e] = qk;
    }
}

// ---------------------------------------------------------------------------
// Attention kernel: coalesced score gather + radix-select top-30.
// ---------------------------------------------------------------------------
__device__ __forceinline__ unsigned score_key(float f) {
    unsigned u = __float_as_uint(f);
    return u ^ (((int)u >> 31) | 0x80000000u);   // order-preserving map
}

__global__ __launch_bounds__(256)
void attn_kernel(const int* __restrict__ seqs,
                 const float* __restrict__ seq_emb,
                 const float* __restrict__ bo) {
    int b = blockIdx.x;
    int tid  = threadIdx.x;          // 256 threads
    int lane = tid & 31, warp = tid >> 5;
    __shared__ float s_scores[LL];
    __shared__ int   s_hist[1024];
    __shared__ float s_cval[LL];
    __shared__ int   s_cidx[LL];
    __shared__ float s_qk[EE];
    __shared__ float s_val[TOPK];
    __shared__ int   s_sel[TOPK];
    __shared__ float s_w[TOPK];
    __shared__ float s_pp[8][EE];
    __shared__ int   s_cnt;
    __shared__ int   s_thr;

    if (tid < EE) s_qk[tid] = g_qk[b * EE + tid];
    // zero histogram while qk loads
    for (int i = tid; i < 1024; i += 256) s_hist[i] = 0;
    if (tid == 0) s_cnt = 0;
    __syncthreads();

    const int* srow = seqs + (long)b * LL;

    // ---- Phase A: scores, 8 lanes cooperate per row (coalesced 128B) ----
    {
        int g = tid >> 3;        // group 0..31
        int c = tid & 7;         // lane within group
        float qk4[4] = { s_qk[c * 4 + 0], s_qk[c * 4 + 1], s_qk[c * 4 + 2], s_qk[c * 4 + 3] };
#pragma unroll 4
        for (int l0 = 0; l0 < LL; l0 += 32) {
            int l = l0 + g;
            int id = srow[l];
            float4 v = reinterpret_cast<const float4*>(seq_emb + (long)id * EE)[c];
            float s = qk4[0] * v.x + qk4[1] * v.y + qk4[2] * v.z + qk4[3] * v.w;
            s += __shfl_down_sync(0xffffffffu, s, 4, 8);
            s += __shfl_down_sync(0xffffffffu, s, 2, 8);
            s += __shfl_down_sync(0xffffffffu, s, 1, 8);
            if (c == 0) s_scores[l] = s;
        }
    }
    __syncthreads();

    // ---- Phase B: histogram of top-10 key bits ----
    for (int i = tid; i < LL; i += 256)
        atomicAdd(&s_hist[score_key(s_scores[i]) >> 22], 1);
    __syncthreads();

    // ---- Phase C: find threshold bin (warp 0, suffix scan from top) ----
    if (warp == 0) {
        int base = 1024 - (lane + 1) * 32;   // lane 0 owns the topmost 32 bins
        int s = 0;
#pragma unroll
        for (int i = 0; i < 32; i++) s += s_hist[base + i];
        int pre = s;                         // inclusive prefix over lanes (top-down)
#pragma unroll
        for (int off = 1; off < 32; off <<= 1) {
            int o = __shfl_up_sync(0xffffffffu, pre, off);
            if (lane >= off) pre += o;
        }
        int preExcl = pre - s;
        if (pre >= TOPK && preExcl < TOPK) { // exactly one lane crosses
            int cum = preExcl;
            for (int i = 31; i >= 0; i--) {
                cum += s_hist[base + i];
                if (cum >= TOPK) { s_thr = base + i; break; }
            }
        }
    }
    __syncthreads();

    // ---- Phase D: compact candidates >= threshold ----
    unsigned thrkey = (unsigned)s_thr << 22;
    for (int i = tid; i < LL; i += 256) {
        float v = s_scores[i];
        if (score_key(v) >= thrkey) {
            int p = atomicAdd(&s_cnt, 1);
            s_cval[p] = v;
            s_cidx[p] = i;
        }
    }
    __syncthreads();

    // ---- Phase E: warp 0 exact top-30 over candidates + softmax ----
    if (warp == 0) {
        int m = s_cnt;
        for (int k = 0; k < TOPK; k++) {
            float bv = -INFINITY; int bi = 0x7fffffff; int bp = -1;
            for (int p = lane; p < m; p += 32) {
                float v = s_cval[p]; int ix = s_cidx[p];
                if (v > bv || (v == bv && ix < bi)) { bv = v; bi = ix; bp = p; }
            }
#pragma unroll
            for (int off = 16; off; off >>= 1) {
                float ov = __shfl_down_sync(0xffffffffu, bv, off);
                int   oi = __shfl_down_sync(0xffffffffu, bi, off);
                int   op = __shfl_down_sync(0xffffffffu, bp, off);
                if (ov > bv || (ov == bv && oi < bi)) { bv = ov; bi = oi; bp = op; }
            }
            int wp = __shfl_sync(0xffffffffu, bp, 0);
            if (lane == 0) { s_val[k] = bv; s_sel[k] = bi; s_cval[wp] = -INFINITY; }
            __syncwarp();
        }
        // softmax over the 30 values (max = s_val[0] by construction)
        float mx = s_val[0];
        float e = (lane < TOPK) ? __expf(s_val[lane] - mx) : 0.f;
        float sum = e;
#pragma unroll
        for (int off = 16; off; off >>= 1) sum += __shfl_xor_sync(0xffffffffu, sum, off);
        if (lane < TOPK) s_w[lane] = e / sum;
    }
    __syncthreads();

    // ---- Phase F: pooled[e] = sum_k w_k * emb[idx_k][e], 8 warps split k ----
    {
        float p = 0.f;
        for (int k = warp; k < TOPK; k += 8)
            p += s_w[k] * seq_emb[(long)srow[s_sel[k]] * EE + lane];
        s_pp[warp][lane] = p;
    }
    __syncthreads();

    // ---- interest = pooled @ Wvo + bo ----
    if (tid < EE) {
        float p = s_pp[0][tid] + s_pp[1][tid] + s_pp[2][tid] + s_pp[3][tid] +
                  s_pp[4][tid] + s_pp[5][tid] + s_pp[6][tid] + s_pp[7][tid];
        s_pp[0][tid] = p;
    }
    __syncthreads();
    if (tid < EE) {
        float acc = bo[tid];
#pragma unroll
        for (int e = 0; e < EE; e++) acc += s_pp[0][e] * g_Wvo[e * EE + tid];
        g_fused[(long)b * 128 + EE + tid] = acc;
    }
}

// ---------------------------------------------------------------------------
// MLP tail with cp.async double-buffered weight staging (unchanged from R2).
// ---------------------------------------------------------------------------
#define STAGE_F 16384

template<int K, int KT>
__device__ __forceinline__ void gemm_single(const float* __restrict__ W,
                                            const float* s_x, int xstride,
                                            float* wbuf, int j, float acc[ROWS]) {
    constexpr int T = K / KT;
    constexpr int F4 = KT * 256 / 4;
    for (int u = threadIdx.x; u < F4; u += 256)
        __pipeline_memcpy_async(&wbuf[u * 4], &W[u * 4], 16);
    __pipeline_commit();
#pragma unroll
    for (int t = 0; t < T; t++) {
        if (t + 1 < T) {
            const float* src = W + (t + 1) * KT * 256;
            float* dst = wbuf + ((t + 1) & 1) * STAGE_F;
            for (int u = threadIdx.x; u < F4; u += 256)
                __pipeline_memcpy_async(&dst[u * 4], &src[u * 4], 16);
            __pipeline_commit();
            __pipeline_wait_prior(1);
        } else {
            __pipeline_wait_prior(0);
        }
        __syncthreads();
        const float* bw = wbuf + (t & 1) * STAGE_F;
#pragma unroll 2
        for (int i0 = 0; i0 < KT; i0 += 4) {
            float4 hv[ROWS];
#pragma unroll
            for (int r = 0; r < ROWS; r++)
                hv[r] = *(const float4*)&s_x[r * xstride + t * KT + i0];
#pragma unroll
            for (int ii = 0; ii < 4; ii++) {
                float w = bw[(i0 + ii) * 256 + j];
#pragma unroll
                for (int r = 0; r < ROWS; r++) {
                    float h = ii == 0 ? hv[r].x : ii == 1 ? hv[r].y : ii == 2 ? hv[r].z : hv[r].w;
                    acc[r] += h * w;
                }
            }
        }
        __syncthreads();
    }
}

__device__ __forceinline__ void gemm_dual(const float* __restrict__ Wa,
                                          const float* __restrict__ Wb,
                                          const float* s_x,
                                          float* wbuf, int j,
                                          float a1[ROWS], float a2[ROWS]) {
    constexpr int KT = 32, T = 8;
    constexpr int F4 = KT * 256 / 4;
    for (int u = threadIdx.x; u < F4; u += 256) {
        __pipeline_memcpy_async(&wbuf[u * 4], &Wa[u * 4], 16);
        __pipeline_memcpy_async(&wbuf[8192 + u * 4], &Wb[u * 4], 16);
    }
    __pipeline_commit();
#pragma unroll
    for (int t = 0; t < T; t++) {
        if (t + 1 < T) {
            const float* sa = Wa + (t + 1) * KT * 256;
            const float* sb = Wb + (t + 1) * KT * 256;
            float* dst = wbuf + ((t + 1) & 1) * STAGE_F;
            for (int u = threadIdx.x; u < F4; u += 256) {
                __pipeline_memcpy_async(&dst[u * 4], &sa[u * 4], 16);
                __pipeline_memcpy_async(&dst[8192 + u * 4], &sb[u * 4], 16);
            }
            __pipeline_commit();
            __pipeline_wait_prior(1);
        } else {
            __pipeline_wait_prior(0);
        }
        __syncthreads();
        const float* bwa = wbuf + (t & 1) * STAGE_F;
        const float* bwb = bwa + 8192;
#pragma unroll 2
        for (int i0 = 0; i0 < KT; i0 += 4) {
            float4 hv[ROWS];
#pragma unroll
            for (int r = 0; r < ROWS; r++)
                hv[r] = *(const float4*)&s_x[r * 256 + t * KT + i0];
#pragma unroll
            for (int ii = 0; ii < 4; ii++) {
                float w1 = bwa[(i0 + ii) * 256 + j];
                float w2 = bwb[(i0 + ii) * 256 + j];
#pragma unroll
                for (int r = 0; r < ROWS; r++) {
                    float h = ii == 0 ? hv[r].x : ii == 1 ? hv[r].y : ii == 2 ? hv[r].z : hv[r].w;
                    a1[r] += h * w1;
                    a2[r] += h * w2;
                }
            }
        }
        __syncthreads();
    }
}

__global__ __launch_bounds__(256)
void mlp_kernel(const float* __restrict__ Wmlp, const float* __restrict__ bmlp,
                const float* __restrict__ W11, const float* __restrict__ b11,
                const float* __restrict__ W12, const float* __restrict__ b12,
                const float* __restrict__ W1p, const float* __restrict__ b1p,
                const float* __restrict__ W21, const float* __restrict__ b21,
                const float* __restrict__ W22, const float* __restrict__ b22,
                const float* __restrict__ W2p, const float* __restrict__ b2p,
                const float* __restrict__ Wout, const float* __restrict__ bout,
                float* __restrict__ out) {
    extern __shared__ float smem[];
    float* s_f = smem;                 // ROWS*128
    float* s_h = smem + 1024;          // ROWS*256
    float* s_q = s_h + 2048;
    float* wbuf = s_q + 2048;          // 2*STAGE_F

    int b0 = blockIdx.x * ROWS;
    int j = threadIdx.x;

    for (int i = j; i < ROWS * 128; i += 256)
        s_f[i] = g_fused[(long)b0 * 128 + i];
    __syncthreads();

    {
        float acc[ROWS];
        float bb = bmlp[j];
#pragma unroll
        for (int r = 0; r < ROWS; r++) acc[r] = bb;
        gemm_single<128, 64>(Wmlp, s_f, 128, wbuf, j, acc);
#pragma unroll
        for (int r = 0; r < ROWS; r++) s_h[r * 256 + j] = fmaxf(acc[r], 0.f);
    }

    const float* Ws1[2] = { W11, W21 };  const float* Bs1[2] = { b11, b21 };
    const float* Ws2[2] = { W12, W22 };  const float* Bs2[2] = { b12, b22 };
    const float* Wsp[2] = { W1p, W2p };  const float* Bsp[2] = { b1p, b2p };

#pragma unroll
    for (int blk = 0; blk < 2; blk++) {
        float a1[ROWS], a2[ROWS];
        float bb1 = Bs1[blk][j], bb2 = Bs2[blk][j];
#pragma unroll
        for (int r = 0; r < ROWS; r++) { a1[r] = bb1; a2[r] = bb2; }
        gemm_dual(Ws1[blk], Ws2[blk], s_h, wbuf, j, a1, a2);
#pragma unroll
        for (int r = 0; r < ROWS; r++) s_q[r * 256 + j] = a1[r] * a2[r];

        float ap[ROWS];
        float bbp = Bsp[blk][j];
#pragma unroll
        for (int r = 0; r < ROWS; r++) ap[r] = bbp;
        gemm_single<256, 64>(Wsp[blk], s_q, 256, wbuf, j, ap);
#pragma unroll
        for (int r = 0; r < ROWS; r++) s_h[r * 256 + j] = s_h[r * 256 + j] + ap[r];
        __syncthreads();
    }

    {
        int w = j >> 5, lane = j & 31;
        float v = 0.f;
#pragma unroll
        for (int c = lane; c < HH; c += 32) v += s_h[w * 256 + c] * Wout[c];
#pragma unroll
        for (int off = 16; off; off >>= 1) v += __shfl_down_sync(0xffffffffu, v, off);
        if (lane == 0) out[b0 + w] = v + bout[0];
    }
}

// ---------------------------------------------------------------------------
extern "C" void kernel_launch(void* const* d_in, const int* in_sizes, int n_in,
                              void* d_out, int out_size) {
    const int*   cats    = (const int*)  d_in[0];
    const float* nums    = (const float*)d_in[1];
    const int*   seqs    = (const int*)  d_in[2];
    const int*   tgt_ids = (const int*)  d_in[3];
    const float* cat_emb = (const float*)d_in[4];
    const float* seq_emb = (const float*)d_in[5];
    const float* Wnum    = (const float*)d_in[6];
    const float* bnum    = (const float*)d_in[7];
    const float* Wq      = (const float*)d_in[8];
    const float* Wk      = (const float*)d_in[9];
    const float* Wv      = (const float*)d_in[10];
    const float* Wo      = (const float*)d_in[11];
    const float* bo      = (const float*)d_in[12];
    const float* Wpool   = (const float*)d_in[13];
    const float* bpool   = (const float*)d_in[14];
    const float* Wmlp    = (const float*)d_in[15];
    const float* bmlp    = (const float*)d_in[16];
    const float* q1_W1   = (const float*)d_in[17];
    const float* q1_b1   = (const float*)d_in[18];
    const float* q1_W2   = (const float*)d_in[19];
    const float* q1_b2   = (const float*)d_in[20];
    const float* q1_Wp   = (const float*)d_in[21];
    const float* q1_bp   = (const float*)d_in[22];
    const float* q2_W1   = (const float*)d_in[23];
    const float* q2_b1   = (const float*)d_in[24];
    const float* q2_W2   = (const float*)d_in[25];
    const float* q2_b2   = (const float*)d_in[26];
    const float* q2_Wp   = (const float*)d_in[27];
    const float* q2_bp   = (const float*)d_in[28];
    const float* Wout    = (const float*)d_in[29];
    const float* bout    = (const float*)d_in[30];
    float* out = (float*)d_out;

    static bool attr_set = false;
    if (!attr_set) {
        cudaFuncSetAttribute(mlp_kernel, cudaFuncAttributeMaxDynamicSharedMemorySize,
                             (1024 + 2048 + 2048 + 2 * STAGE_F) * sizeof(float));
        attr_set = true;
    }

    precompute_kernel<<<1, 1024>>>(Wq, Wk, Wv, Wo);
    front_kernel<<<BB, 128>>>(cats, nums, tgt_ids, cat_emb, Wnum, bnum, Wpool, bpool);
    attn_kernel<<<BB, 256>>>(seqs, seq_emb, bo);
    mlp_kernel<<<BB / ROWS, 256, (1024 + 2048 + 2048 + 2 * STAGE_F) * sizeof(float)>>>(
        Wmlp, bmlp,
        q1_W1, q1_b1, q1_W2, q1_b2, q1_Wp, q1_bp,
        q2_W1, q2_b1, q2_W2, q2_b2, q2_Wp, q2_bp,
        Wout, bout, out);
}

// round 4
// speedup vs baseline: 2.0876x; 1.5766x over previous
#include <cuda_runtime.h>
#include <cuda_pipeline.h>
#include <math.h>

// Problem constants
#define BB    1024
#define LL    1024
#define NCAT  20
#define NNUM  10
#define EE    32
#define HH    256
#define TOPK  30
#define ROWS  8

// Device scratch (no allocations allowed)
__device__ float g_fused[BB * 128];   // [tgt_e | interest | cat_pool | num_e]
__device__ float g_qk[BB * EE];       // tgt_e @ (Wq Wk^T) / sqrt(128)
__device__ float g_Wqk[EE * EE];
__device__ float g_Wvo[EE * EE];

// ---------------------------------------------------------------------------
// Precompute fused 32x32 matrices, PARALLEL + COALESCED.
//   block 0: Wqk = (Wq @ Wk^T) / sqrt(128)     block 1: Wvo = Wv @ Wo
// All global loads coalesced; Wk staged transposed with +1 padding so the
// inner product reads are bank-conflict-free.
// ---------------------------------------------------------------------------
__global__ __launch_bounds__(256)
void precompute_kernel(const float* __restrict__ Wq,
                       const float* __restrict__ Wk,
                       const float* __restrict__ Wv,
                       const float* __restrict__ Wo) {
    __shared__ float sA[32 * 128];     // row-major [e1][a]
    __shared__ float sB[128 * 33];     // padded   [a][e2]
    int tid = threadIdx.x;

    if (blockIdx.x == 0) {
        for (int i = tid; i < 4096; i += 256) sA[i] = Wq[i];
        for (int i = tid; i < 4096; i += 256) {
            int e2 = i >> 7, a = i & 127;          // Wk[e2][a], coalesced read
            sB[a * 33 + e2] = Wk[i];
        }
        __syncthreads();
        for (int o = tid; o < 1024; o += 256) {
            int e1 = o >> 5, e2 = o & 31;
            float s = 0.f;
#pragma unroll 8
            for (int a = 0; a < 128; a++)
                s += sA[e1 * 128 + a] * sB[a * 33 + e2];
            g_Wqk[o] = s * 0.08838834764831845f;   // 1/sqrt(128)
        }
    } else {
        for (int i = tid; i < 4096; i += 256) sA[i] = Wv[i];
        for (int i = tid; i < 4096; i += 256) {
            int a = i >> 5, e2 = i & 31;           // Wo[a][e2], coalesced read
            sB[a * 33 + e2] = Wo[i];
        }
        __syncthreads();
        for (int o = tid; o < 1024; o += 256) {
            int e1 = o >> 5, e2 = o & 31;
            float s = 0.f;
#pragma unroll 8
            for (int a = 0; a < 128; a++)
                s += sA[e1 * 128 + a] * sB[a * 33 + e2];
            g_Wvo[o] = s;
        }
    }
}

// ---------------------------------------------------------------------------
// Front kernel: per-batch-row. tgt gather, cat_pool, num_e, qk vector.
// ---------------------------------------------------------------------------
__global__ void front_kernel(const int* __restrict__ cats,
                             const float* __restrict__ nums,
                             const int* __restrict__ tgt_ids,
                             const float* __restrict__ cat_emb,
                             const float* __restrict__ Wnum,
                             const float* __restrict__ bnum,
                             const float* __restrict__ Wpool,
                             const float* __restrict__ bpool) {
    int b = blockIdx.x;
    int tid = threadIdx.x;          // 128 threads
    __shared__ float s_cat[NCAT * EE];  // 640
    __shared__ float s_tgt[EE];
    __shared__ float s_part[4][EE];

    for (int i = tid; i < NCAT * EE; i += 128)
        s_cat[i] = cat_emb[(long)cats[b * NCAT + (i >> 5)] * EE + (i & 31)];
    if (tid < EE)
        s_tgt[tid] = cat_emb[(long)tgt_ids[b] * EE + tid];
    __syncthreads();

    int e = tid & 31, p = tid >> 5;
    float acc = 0.f;
#pragma unroll 4
    for (int i = p * 160; i < (p + 1) * 160; i++)
        acc += s_cat[i] * Wpool[i * EE + e];
    s_part[p][e] = acc;
    __syncthreads();

    if (tid < EE) {
        float cp = bpool[e] + s_part[0][e] + s_part[1][e] + s_part[2][e] + s_part[3][e];
        float ne = bnum[e];
#pragma unroll
        for (int j = 0; j < NNUM; j++) ne += nums[b * NNUM + j] * Wnum[j * EE + e];
        float qk = 0.f;
#pragma unroll
        for (int e2 = 0; e2 < EE; e2++) qk += s_tgt[e2] * g_Wqk[e2 * EE + e];
        float* fr = g_fused + (long)b * 128;
        fr[e]       = s_tgt[e];
        fr[64 + e]  = cp;
        fr[96 + e]  = ne;
        g_qk[b * EE + e] = qk;
    }
}

// ---------------------------------------------------------------------------
// Attention kernel: coalesced score gather + radix-select top-30.
// ---------------------------------------------------------------------------
__device__ __forceinline__ unsigned score_key(float f) {
    unsigned u = __float_as_uint(f);
    return u ^ (((int)u >> 31) | 0x80000000u);   // order-preserving map
}

__global__ __launch_bounds__(256)
void attn_kernel(const int* __restrict__ seqs,
                 const float* __restrict__ seq_emb,
                 const float* __restrict__ bo) {
    int b = blockIdx.x;
    int tid  = threadIdx.x;          // 256 threads
    int lane = tid & 31, warp = tid >> 5;
    __shared__ float s_scores[LL];
    __shared__ int   s_hist[1024];
    __shared__ float s_cval[LL];
    __shared__ int   s_cidx[LL];
    __shared__ float s_qk[EE];
    __shared__ float s_val[TOPK];
    __shared__ int   s_sel[TOPK];
    __shared__ float s_w[TOPK];
    __shared__ float s_pp[8][EE];
    __shared__ int   s_cnt;
    __shared__ int   s_thr;

    if (tid < EE) s_qk[tid] = g_qk[b * EE + tid];
    for (int i = tid; i < 1024; i += 256) s_hist[i] = 0;
    if (tid == 0) s_cnt = 0;
    __syncthreads();

    const int* srow = seqs + (long)b * LL;

    // ---- Phase A: scores, 8 lanes cooperate per row (coalesced 128B) ----
    {
        int g = tid >> 3;        // group 0..31
        int c = tid & 7;         // lane within group
        float qk4[4] = { s_qk[c * 4 + 0], s_qk[c * 4 + 1], s_qk[c * 4 + 2], s_qk[c * 4 + 3] };
#pragma unroll 4
        for (int l0 = 0; l0 < LL; l0 += 32) {
            int l = l0 + g;
            int id = srow[l];
            float4 v = reinterpret_cast<const float4*>(seq_emb + (long)id * EE)[c];
            float s = qk4[0] * v.x + qk4[1] * v.y + qk4[2] * v.z + qk4[3] * v.w;
            s += __shfl_down_sync(0xffffffffu, s, 4, 8);
            s += __shfl_down_sync(0xffffffffu, s, 2, 8);
            s += __shfl_down_sync(0xffffffffu, s, 1, 8);
            if (c == 0) s_scores[l] = s;
        }
    }
    __syncthreads();

    // ---- Phase B: histogram of top-10 key bits ----
    for (int i = tid; i < LL; i += 256)
        atomicAdd(&s_hist[score_key(s_scores[i]) >> 22], 1);
    __syncthreads();

    // ---- Phase C: find threshold bin (warp 0, suffix scan from top) ----
    if (warp == 0) {
        int base = 1024 - (lane + 1) * 32;   // lane 0 owns the topmost 32 bins
        int s = 0;
#pragma unroll
        for (int i = 0; i < 32; i++) s += s_hist[base + i];
        int pre = s;
#pragma unroll
        for (int off = 1; off < 32; off <<= 1) {
            int o = __shfl_up_sync(0xffffffffu, pre, off);
            if (lane >= off) pre += o;
        }
        int preExcl = pre - s;
        if (pre >= TOPK && preExcl < TOPK) {
            int cum = preExcl;
            for (int i = 31; i >= 0; i--) {
                cum += s_hist[base + i];
                if (cum >= TOPK) { s_thr = base + i; break; }
            }
        }
    }
    __syncthreads();

    // ---- Phase D: compact candidates >= threshold ----
    unsigned thrkey = (unsigned)s_thr << 22;
    for (int i = tid; i < LL; i += 256) {
        float v = s_scores[i];
        if (score_key(v) >= thrkey) {
            int p = atomicAdd(&s_cnt, 1);
            s_cval[p] = v;
            s_cidx[p] = i;
        }
    }
    __syncthreads();

    // ---- Phase E: warp 0 exact top-30 over candidates + softmax ----
    if (warp == 0) {
        int m = s_cnt;
        for (int k = 0; k < TOPK; k++) {
            float bv = -INFINITY; int bi = 0x7fffffff; int bp = -1;
            for (int p = lane; p < m; p += 32) {
                float v = s_cval[p]; int ix = s_cidx[p];
                if (v > bv || (v == bv && ix < bi)) { bv = v; bi = ix; bp = p; }
            }
#pragma unroll
            for (int off = 16; off; off >>= 1) {
                float ov = __shfl_down_sync(0xffffffffu, bv, off);
                int   oi = __shfl_down_sync(0xffffffffu, bi, off);
                int   op = __shfl_down_sync(0xffffffffu, bp, off);
                if (ov > bv || (ov == bv && oi < bi)) { bv = ov; bi = oi; bp = op; }
            }
            int wp = __shfl_sync(0xffffffffu, bp, 0);
            if (lane == 0) { s_val[k] = bv; s_sel[k] = bi; s_cval[wp] = -INFINITY; }
            __syncwarp();
        }
        float mx = s_val[0];
        float e = (lane < TOPK) ? __expf(s_val[lane] - mx) : 0.f;
        float sum = e;
#pragma unroll
        for (int off = 16; off; off >>= 1) sum += __shfl_xor_sync(0xffffffffu, sum, off);
        if (lane < TOPK) s_w[lane] = e / sum;
    }
    __syncthreads();

    // ---- Phase F: pooled[e] = sum_k w_k * emb[idx_k][e], 8 warps split k ----
    {
        float p = 0.f;
        for (int k = warp; k < TOPK; k += 8)
            p += s_w[k] * seq_emb[(long)srow[s_sel[k]] * EE + lane];
        s_pp[warp][lane] = p;
    }
    __syncthreads();

    if (tid < EE) {
        float p = s_pp[0][tid] + s_pp[1][tid] + s_pp[2][tid] + s_pp[3][tid] +
                  s_pp[4][tid] + s_pp[5][tid] + s_pp[6][tid] + s_pp[7][tid];
        s_pp[0][tid] = p;
    }
    __syncthreads();
    if (tid < EE) {
        float acc = bo[tid];
#pragma unroll
        for (int e = 0; e < EE; e++) acc += s_pp[0][e] * g_Wvo[e * EE + tid];
        g_fused[(long)b * 128 + EE + tid] = acc;
    }
}

// ---------------------------------------------------------------------------
// MLP tail with cp.async double-buffered weight staging (unchanged).
// ---------------------------------------------------------------------------
#define STAGE_F 16384

template<int K, int KT>
__device__ __forceinline__ void gemm_single(const float* __restrict__ W,
                                            const float* s_x, int xstride,
                                            float* wbuf, int j, float acc[ROWS]) {
    constexpr int T = K / KT;
    constexpr int F4 = KT * 256 / 4;
    for (int u = threadIdx.x; u < F4; u += 256)
        __pipeline_memcpy_async(&wbuf[u * 4], &W[u * 4], 16);
    __pipeline_commit();
#pragma unroll
    for (int t = 0; t < T; t++) {
        if (t + 1 < T) {
            const float* src = W + (t + 1) * KT * 256;
            float* dst = wbuf + ((t + 1) & 1) * STAGE_F;
            for (int u = threadIdx.x; u < F4; u += 256)
                __pipeline_memcpy_async(&dst[u * 4], &src[u * 4], 16);
            __pipeline_commit();
            __pipeline_wait_prior(1);
        } else {
            __pipeline_wait_prior(0);
        }
        __syncthreads();
        const float* bw = wbuf + (t & 1) * STAGE_F;
#pragma unroll 2
        for (int i0 = 0; i0 < KT; i0 += 4) {
            float4 hv[ROWS];
#pragma unroll
            for (int r = 0; r < ROWS; r++)
                hv[r] = *(const float4*)&s_x[r * xstride + t * KT + i0];
#pragma unroll
            for (int ii = 0; ii < 4; ii++) {
                float w = bw[(i0 + ii) * 256 + j];
#pragma unroll
                for (int r = 0; r < ROWS; r++) {
                    float h = ii == 0 ? hv[r].x : ii == 1 ? hv[r].y : ii == 2 ? hv[r].z : hv[r].w;
                    acc[r] += h * w;
                }
            }
        }
        __syncthreads();
    }
}

__device__ __forceinline__ void gemm_dual(const float* __restrict__ Wa,
                                          const float* __restrict__ Wb,
                                          const float* s_x,
                                          float* wbuf, int j,
                                          float a1[ROWS], float a2[ROWS]) {
    constexpr int KT = 32, T = 8;
    constexpr int F4 = KT * 256 / 4;
    for (int u = threadIdx.x; u < F4; u += 256) {
        __pipeline_memcpy_async(&wbuf[u * 4], &Wa[u * 4], 16);
        __pipeline_memcpy_async(&wbuf[8192 + u * 4], &Wb[u * 4], 16);
    }
    __pipeline_commit();
#pragma unroll
    for (int t = 0; t < T; t++) {
        if (t + 1 < T) {
            const float* sa = Wa + (t + 1) * KT * 256;
            const float* sb = Wb + (t + 1) * KT * 256;
            float* dst = wbuf + ((t + 1) & 1) * STAGE_F;
            for (int u = threadIdx.x; u < F4; u += 256) {
                __pipeline_memcpy_async(&dst[u * 4], &sa[u * 4], 16);
                __pipeline_memcpy_async(&dst[8192 + u * 4], &sb[u * 4], 16);
            }
            __pipeline_commit();
            __pipeline_wait_prior(1);
        } else {
            __pipeline_wait_prior(0);
        }
        __syncthreads();
        const float* bwa = wbuf + (t & 1) * STAGE_F;
        const float* bwb = bwa + 8192;
#pragma unroll 2
        for (int i0 = 0; i0 < KT; i0 += 4) {
            float4 hv[ROWS];
#pragma unroll
            for (int r = 0; r < ROWS; r++)
                hv[r] = *(const float4*)&s_x[r * 256 + t * KT + i0];
#pragma unroll
            for (int ii = 0; ii < 4; ii++) {
                float w1 = bwa[(i0 + ii) * 256 + j];
                float w2 = bwb[(i0 + ii) * 256 + j];
#pragma unroll
                for (int r = 0; r < ROWS; r++) {
                    float h = ii == 0 ? hv[r].x : ii == 1 ? hv[r].y : ii == 2 ? hv[r].z : hv[r].w;
                    a1[r] += h * w1;
                    a2[r] += h * w2;
                }
            }
        }
        __syncthreads();
    }
}

__global__ __launch_bounds__(256)
void mlp_kernel(const float* __restrict__ Wmlp, const float* __restrict__ bmlp,
                const float* __restrict__ W11, const float* __restrict__ b11,
                const float* __restrict__ W12, const float* __restrict__ b12,
                const float* __restrict__ W1p, const float* __restrict__ b1p,
                const float* __restrict__ W21, const float* __restrict__ b21,
                const float* __restrict__ W22, const float* __restrict__ b22,
                const float* __restrict__ W2p, const float* __restrict__ b2p,
                const float* __restrict__ Wout, const float* __restrict__ bout,
                float* __restrict__ out) {
    extern __shared__ float smem[];
    float* s_f = smem;                 // ROWS*128
    float* s_h = smem + 1024;          // ROWS*256
    float* s_q = s_h + 2048;
    float* wbuf = s_q + 2048;          // 2*STAGE_F

    int b0 = blockIdx.x * ROWS;
    int j = threadIdx.x;

    for (int i = j; i < ROWS * 128; i += 256)
        s_f[i] = g_fused[(long)b0 * 128 + i];
    __syncthreads();

    {
        float acc[ROWS];
        float bb = bmlp[j];
#pragma unroll
        for (int r = 0; r < ROWS; r++) acc[r] = bb;
        gemm_single<128, 64>(Wmlp, s_f, 128, wbuf, j, acc);
#pragma unroll
        for (int r = 0; r < ROWS; r++) s_h[r * 256 + j] = fmaxf(acc[r], 0.f);
    }

    const float* Ws1[2] = { W11, W21 };  const float* Bs1[2] = { b11, b21 };
    const float* Ws2[2] = { W12, W22 };  const float* Bs2[2] = { b12, b22 };
    const float* Wsp[2] = { W1p, W2p };  const float* Bsp[2] = { b1p, b2p };

#pragma unroll
    for (int blk = 0; blk < 2; blk++) {
        float a1[ROWS], a2[ROWS];
        float bb1 = Bs1[blk][j], bb2 = Bs2[blk][j];
#pragma unroll
        for (int r = 0; r < ROWS; r++) { a1[r] = bb1; a2[r] = bb2; }
        gemm_dual(Ws1[blk], Ws2[blk], s_h, wbuf, j, a1, a2);
#pragma unroll
        for (int r = 0; r < ROWS; r++) s_q[r * 256 + j] = a1[r] * a2[r];

        float ap[ROWS];
        float bbp = Bsp[blk][j];
#pragma unroll
        for (int r = 0; r < ROWS; r++) ap[r] = bbp;
        gemm_single<256, 64>(Wsp[blk], s_q, 256, wbuf, j, ap);
#pragma unroll
        for (int r = 0; r < ROWS; r++) s_h[r * 256 + j] = s_h[r * 256 + j] + ap[r];
        __syncthreads();
    }

    {
        int w = j >> 5, lane = j & 31;
        float v = 0.f;
#pragma unroll
        for (int c = lane; c < HH; c += 32) v += s_h[w * 256 + c] * Wout[c];
#pragma unroll
        for (int off = 16; off; off >>= 1) v += __shfl_down_sync(0xffffffffu, v, off);
        if (lane == 0) out[b0 + w] = v + bout[0];
    }
}

// ---------------------------------------------------------------------------
extern "C" void kernel_launch(void* const* d_in, const int* in_sizes, int n_in,
                              void* d_out, int out_size) {
    const int*   cats    = (const int*)  d_in[0];
    const float* nums    = (const float*)d_in[1];
    const int*   seqs    = (const int*)  d_in[2];
    const int*   tgt_ids = (const int*)  d_in[3];
    const float* cat_emb = (const float*)d_in[4];
    const float* seq_emb = (const float*)d_in[5];
    const float* Wnum    = (const float*)d_in[6];
    const float* bnum    = (const float*)d_in[7];
    const float* Wq      = (const float*)d_in[8];
    const float* Wk      = (const float*)d_in[9];
    const float* Wv      = (const float*)d_in[10];
    const float* Wo      = (const float*)d_in[11];
    const float* bo      = (const float*)d_in[12];
    const float* Wpool   = (const float*)d_in[13];
    const float* bpool   = (const float*)d_in[14];
    const float* Wmlp    = (const float*)d_in[15];
    const float* bmlp    = (const float*)d_in[16];
    const float* q1_W1   = (const float*)d_in[17];
    const float* q1_b1   = (const float*)d_in[18];
    const float* q1_W2   = (const float*)d_in[19];
    const float* q1_b2   = (const float*)d_in[20];
    const float* q1_Wp   = (const float*)d_in[21];
    const float* q1_bp   = (const float*)d_in[22];
    const float* q2_W1   = (const float*)d_in[23];
    const float* q2_b1   = (const float*)d_in[24];
    const float* q2_W2   = (const float*)d_in[25];
    const float* q2_b2   = (const float*)d_in[26];
    const float* q2_Wp   = (const float*)d_in[27];
    const float* q2_bp   = (const float*)d_in[28];
    const float* Wout    = (const float*)d_in[29];
    const float* bout    = (const float*)d_in[30];
    float* out = (float*)d_out;

    cudaFuncSetAttribute(mlp_kernel, cudaFuncAttributeMaxDynamicSharedMemorySize,
                         (1024 + 2048 + 2048 + 2 * STAGE_F) * sizeof(float));

    precompute_kernel<<<2, 256>>>(Wq, Wk, Wv, Wo);
    front_kernel<<<BB, 128>>>(cats, nums, tgt_ids, cat_emb, Wnum, bnum, Wpool, bpool);
    attn_kernel<<<BB, 256>>>(seqs, seq_emb, bo);
    mlp_kernel<<<BB / ROWS, 256, (1024 + 2048 + 2048 + 2 * STAGE_F) * sizeof(float)>>>(
        Wmlp, bmlp,
        q1_W1, q1_b1, q1_W2, q1_b2, q1_Wp, q1_bp,
        q2_W1, q2_b1, q2_W2, q2_b2, q2_Wp, q2_bp,
        Wout, bout, out);
}

// round 5
// speedup vs baseline: 2.1236x; 1.0173x over previous
#include <cuda_runtime.h>
#include <cuda_pipeline.h>
#include <math.h>

// Problem constants
#define BB    1024
#define LL    1024
#define NCAT  20
#define NNUM  10
#define EE    32
#define HH    256
#define TOPK  30
#define ROWS  8

typedef unsigned long long ull;

// Packed fp32x2 helpers (Blackwell sm_100+; exact fp32 semantics per lane)
__device__ __forceinline__ ull pack2s(float v) {
    ull r; asm("mov.b64 %0, {%1, %1};" : "=l"(r) : "f"(v)); return r;
}
__device__ __forceinline__ ull pack2(float a, float b) {
    ull r; asm("mov.b64 %0, {%1, %2};" : "=l"(r) : "f"(a), "f"(b)); return r;
}
__device__ __forceinline__ void unpack2(ull p, float& a, float& b) {
    asm("mov.b64 {%0, %1}, %2;" : "=f"(a), "=f"(b) : "l"(p));
}
#define FMA2(d, a, b, c) asm("fma.rn.f32x2 %0, %1, %2, %3;" : "=l"(d) : "l"(a), "l"(b), "l"(c))
#define MUL2(d, a, b)    asm("mul.rn.f32x2 %0, %1, %2;"     : "=l"(d) : "l"(a), "l"(b))
#define ADD2(d, a, b)    asm("add.rn.f32x2 %0, %1, %2;"     : "=l"(d) : "l"(a), "l"(b))

// Device scratch (no allocations allowed)
__device__ float g_fused[BB * 128];   // [tgt_e | interest | cat_pool | num_e]
__device__ float g_qk[BB * EE];       // tgt_e @ (Wq Wk^T) / sqrt(128)
__device__ float g_Wqk[EE * EE];
__device__ float g_Wvo[EE * EE];

// ---------------------------------------------------------------------------
// Precompute fused 32x32 matrices (parallel + coalesced) — unchanged from R4.
// ---------------------------------------------------------------------------
__global__ __launch_bounds__(256)
void precompute_kernel(const float* __restrict__ Wq,
                       const float* __restrict__ Wk,
                       const float* __restrict__ Wv,
                       const float* __restrict__ Wo) {
    __shared__ float sA[32 * 128];     // row-major [e1][a]
    __shared__ float sB[128 * 33];     // padded   [a][e2]
    int tid = threadIdx.x;

    if (blockIdx.x == 0) {
        for (int i = tid; i < 4096; i += 256) sA[i] = Wq[i];
        for (int i = tid; i < 4096; i += 256) {
            int e2 = i >> 7, a = i & 127;
            sB[a * 33 + e2] = Wk[i];
        }
        __syncthreads();
        for (int o = tid; o < 1024; o += 256) {
            int e1 = o >> 5, e2 = o & 31;
            float s = 0.f;
#pragma unroll 8
            for (int a = 0; a < 128; a++)
                s += sA[e1 * 128 + a] * sB[a * 33 + e2];
            g_Wqk[o] = s * 0.08838834764831845f;
        }
    } else {
        for (int i = tid; i < 4096; i += 256) sA[i] = Wv[i];
        for (int i = tid; i < 4096; i += 256) {
            int a = i >> 5, e2 = i & 31;
            sB[a * 33 + e2] = Wo[i];
        }
        __syncthreads();
        for (int o = tid; o < 1024; o += 256) {
            int e1 = o >> 5, e2 = o & 31;
            float s = 0.f;
#pragma unroll 8
            for (int a = 0; a < 128; a++)
                s += sA[e1 * 128 + a] * sB[a * 33 + e2];
            g_Wvo[o] = s;
        }
    }
}

// ---------------------------------------------------------------------------
// Front kernel — unchanged from R4.
// ---------------------------------------------------------------------------
__global__ void front_kernel(const int* __restrict__ cats,
                             const float* __restrict__ nums,
                             const int* __restrict__ tgt_ids,
                             const float* __restrict__ cat_emb,
                             const float* __restrict__ Wnum,
                             const float* __restrict__ bnum,
                             const float* __restrict__ Wpool,
                             const float* __restrict__ bpool) {
    int b = blockIdx.x;
    int tid = threadIdx.x;          // 128 threads
    __shared__ float s_cat[NCAT * EE];
    __shared__ float s_tgt[EE];
    __shared__ float s_part[4][EE];

    for (int i = tid; i < NCAT * EE; i += 128)
        s_cat[i] = cat_emb[(long)cats[b * NCAT + (i >> 5)] * EE + (i & 31)];
    if (tid < EE)
        s_tgt[tid] = cat_emb[(long)tgt_ids[b] * EE + tid];
    __syncthreads();

    int e = tid & 31, p = tid >> 5;
    float acc = 0.f;
#pragma unroll 4
    for (int i = p * 160; i < (p + 1) * 160; i++)
        acc += s_cat[i] * Wpool[i * EE + e];
    s_part[p][e] = acc;
    __syncthreads();

    if (tid < EE) {
        float cp = bpool[e] + s_part[0][e] + s_part[1][e] + s_part[2][e] + s_part[3][e];
        float ne = bnum[e];
#pragma unroll
        for (int j = 0; j < NNUM; j++) ne += nums[b * NNUM + j] * Wnum[j * EE + e];
        float qk = 0.f;
#pragma unroll
        for (int e2 = 0; e2 < EE; e2++) qk += s_tgt[e2] * g_Wqk[e2 * EE + e];
        float* fr = g_fused + (long)b * 128;
        fr[e]       = s_tgt[e];
        fr[64 + e]  = cp;
        fr[96 + e]  = ne;
        g_qk[b * EE + e] = qk;
    }
}

// ---------------------------------------------------------------------------
// Attention kernel — unchanged from R4.
// ---------------------------------------------------------------------------
__device__ __forceinline__ unsigned score_key(float f) {
    unsigned u = __float_as_uint(f);
    return u ^ (((int)u >> 31) | 0x80000000u);
}

__global__ __launch_bounds__(256)
void attn_kernel(const int* __restrict__ seqs,
                 const float* __restrict__ seq_emb,
                 const float* __restrict__ bo) {
    int b = blockIdx.x;
    int tid  = threadIdx.x;
    int lane = tid & 31, warp = tid >> 5;
    __shared__ float s_scores[LL];
    __shared__ int   s_hist[1024];
    __shared__ float s_cval[LL];
    __shared__ int   s_cidx[LL];
    __shared__ float s_qk[EE];
    __shared__ float s_val[TOPK];
    __shared__ int   s_sel[TOPK];
    __shared__ float s_w[TOPK];
    __shared__ float s_pp[8][EE];
    __shared__ int   s_cnt;
    __shared__ int   s_thr;

    if (tid < EE) s_qk[tid] = g_qk[b * EE + tid];
    for (int i = tid; i < 1024; i += 256) s_hist[i] = 0;
    if (tid == 0) s_cnt = 0;
    __syncthreads();

    const int* srow = seqs + (long)b * LL;

    {
        int g = tid >> 3;
        int c = tid & 7;
        float qk4[4] = { s_qk[c * 4 + 0], s_qk[c * 4 + 1], s_qk[c * 4 + 2], s_qk[c * 4 + 3] };
#pragma unroll 4
        for (int l0 = 0; l0 < LL; l0 += 32) {
            int l = l0 + g;
            int id = srow[l];
            float4 v = reinterpret_cast<const float4*>(seq_emb + (long)id * EE)[c];
            float s = qk4[0] * v.x + qk4[1] * v.y + qk4[2] * v.z + qk4[3] * v.w;
            s += __shfl_down_sync(0xffffffffu, s, 4, 8);
            s += __shfl_down_sync(0xffffffffu, s, 2, 8);
            s += __shfl_down_sync(0xffffffffu, s, 1, 8);
            if (c == 0) s_scores[l] = s;
        }
    }
    __syncthreads();

    for (int i = tid; i < LL; i += 256)
        atomicAdd(&s_hist[score_key(s_scores[i]) >> 22], 1);
    __syncthreads();

    if (warp == 0) {
        int base = 1024 - (lane + 1) * 32;
        int s = 0;
#pragma unroll
        for (int i = 0; i < 32; i++) s += s_hist[base + i];
        int pre = s;
#pragma unroll
        for (int off = 1; off < 32; off <<= 1) {
            int o = __shfl_up_sync(0xffffffffu, pre, off);
            if (lane >= off) pre += o;
        }
        int preExcl = pre - s;
        if (pre >= TOPK && preExcl < TOPK) {
            int cum = preExcl;
            for (int i = 31; i >= 0; i--) {
                cum += s_hist[base + i];
                if (cum >= TOPK) { s_thr = base + i; break; }
            }
        }
    }
    __syncthreads();

    unsigned thrkey = (unsigned)s_thr << 22;
    for (int i = tid; i < LL; i += 256) {
        float v = s_scores[i];
        if (score_key(v) >= thrkey) {
            int p = atomicAdd(&s_cnt, 1);
            s_cval[p] = v;
            s_cidx[p] = i;
        }
    }
    __syncthreads();

    if (warp == 0) {
        int m = s_cnt;
        for (int k = 0; k < TOPK; k++) {
            float bv = -INFINITY; int bi = 0x7fffffff; int bp = -1;
            for (int p = lane; p < m; p += 32) {
                float v = s_cval[p]; int ix = s_cidx[p];
                if (v > bv || (v == bv && ix < bi)) { bv = v; bi = ix; bp = p; }
            }
#pragma unroll
            for (int off = 16; off; off >>= 1) {
                float ov = __shfl_down_sync(0xffffffffu, bv, off);
                int   oi = __shfl_down_sync(0xffffffffu, bi, off);
                int   op = __shfl_down_sync(0xffffffffu, bp, off);
                if (ov > bv || (ov == bv && oi < bi)) { bv = ov; bi = oi; bp = op; }
            }
            int wp = __shfl_sync(0xffffffffu, bp, 0);
            if (lane == 0) { s_val[k] = bv; s_sel[k] = bi; s_cval[wp] = -INFINITY; }
            __syncwarp();
        }
        float mx = s_val[0];
        float e = (lane < TOPK) ? __expf(s_val[lane] - mx) : 0.f;
        float sum = e;
#pragma unroll
        for (int off = 16; off; off >>= 1) sum += __shfl_xor_sync(0xffffffffu, sum, off);
        if (lane < TOPK) s_w[lane] = e / sum;
    }
    __syncthreads();

    {
        float p = 0.f;
        for (int k = warp; k < TOPK; k += 8)
            p += s_w[k] * seq_emb[(long)srow[s_sel[k]] * EE + lane];
        s_pp[warp][lane] = p;
    }
    __syncthreads();

    if (tid < EE) {
        float p = s_pp[0][tid] + s_pp[1][tid] + s_pp[2][tid] + s_pp[3][tid] +
                  s_pp[4][tid] + s_pp[5][tid] + s_pp[6][tid] + s_pp[7][tid];
        s_pp[0][tid] = p;
    }
    __syncthreads();
    if (tid < EE) {
        float acc = bo[tid];
#pragma unroll
        for (int e = 0; e < EE; e++) acc += s_pp[0][e] * g_Wvo[e * EE + tid];
        g_fused[(long)b * 128 + EE + tid] = acc;
    }
}

// ---------------------------------------------------------------------------
// MLP tail: cp.async weight pipeline + packed f32x2 math.
// Activations stored INTERLEAVED: s_x[i*8 + r] (column-major over the 8 rows)
// so row-pairs load directly as 64-bit lanes for fma.rn.f32x2.
// ---------------------------------------------------------------------------
#define STAGE_F 16384

template<int K, int KT>
__device__ __forceinline__ void gemm_single_p(const float* __restrict__ W,
                                              const float* s_x,   // interleaved [K][8]
                                              float* wbuf, int j, ull acc[4]) {
    constexpr int T = K / KT;
    constexpr int F4 = KT * 256 / 4;
    for (int u = threadIdx.x; u < F4; u += 256)
        __pipeline_memcpy_async(&wbuf[u * 4], &W[u * 4], 16);
    __pipeline_commit();
#pragma unroll
    for (int t = 0; t < T; t++) {
        if (t + 1 < T) {
            const float* src = W + (t + 1) * KT * 256;
            float* dst = wbuf + ((t + 1) & 1) * STAGE_F;
            for (int u = threadIdx.x; u < F4; u += 256)
                __pipeline_memcpy_async(&dst[u * 4], &src[u * 4], 16);
            __pipeline_commit();
            __pipeline_wait_prior(1);
        } else {
            __pipeline_wait_prior(0);
        }
        __syncthreads();
        const float* bw = wbuf + (t & 1) * STAGE_F;
        const float* xs = s_x + t * KT * 8;
#pragma unroll 4
        for (int i = 0; i < KT; i++) {
            ulonglong2 xa = *(const ulonglong2*)(xs + i * 8);
            ulonglong2 xb = *(const ulonglong2*)(xs + i * 8 + 4);
            ull wp = pack2s(bw[i * 256 + j]);
            FMA2(acc[0], xa.x, wp, acc[0]);
            FMA2(acc[1], xa.y, wp, acc[1]);
            FMA2(acc[2], xb.x, wp, acc[2]);
            FMA2(acc[3], xb.y, wp, acc[3]);
        }
        __syncthreads();
    }
}

__device__ __forceinline__ void gemm_dual_p(const float* __restrict__ Wa,
                                            const float* __restrict__ Wb,
                                            const float* s_x,   // interleaved [256][8]
                                            float* wbuf, int j,
                                            ull a1[4], ull a2[4]) {
    constexpr int KT = 32, T = 8;
    constexpr int F4 = KT * 256 / 4;
    for (int u = threadIdx.x; u < F4; u += 256) {
        __pipeline_memcpy_async(&wbuf[u * 4], &Wa[u * 4], 16);
        __pipeline_memcpy_async(&wbuf[8192 + u * 4], &Wb[u * 4], 16);
    }
    __pipeline_commit();
#pragma unroll
    for (int t = 0; t < T; t++) {
        if (t + 1 < T) {
            const float* sa = Wa + (t + 1) * KT * 256;
            const float* sb = Wb + (t + 1) * KT * 256;
            float* dst = wbuf + ((t + 1) & 1) * STAGE_F;
            for (int u = threadIdx.x; u < F4; u += 256) {
                __pipeline_memcpy_async(&dst[u * 4], &sa[u * 4], 16);
                __pipeline_memcpy_async(&dst[8192 + u * 4], &sb[u * 4], 16);
            }
            __pipeline_commit();
            __pipeline_wait_prior(1);
        } else {
            __pipeline_wait_prior(0);
        }
        __syncthreads();
        const float* bwa = wbuf + (t & 1) * STAGE_F;
        const float* bwb = bwa + 8192;
        const float* xs = s_x + t * KT * 8;
#pragma unroll 4
        for (int i = 0; i < KT; i++) {
            ulonglong2 xa = *(const ulonglong2*)(xs + i * 8);
            ulonglong2 xb = *(const ulonglong2*)(xs + i * 8 + 4);
            ull w1 = pack2s(bwa[i * 256 + j]);
            ull w2 = pack2s(bwb[i * 256 + j]);
            FMA2(a1[0], xa.x, w1, a1[0]);
            FMA2(a1[1], xa.y, w1, a1[1]);
            FMA2(a1[2], xb.x, w1, a1[2]);
            FMA2(a1[3], xb.y, w1, a1[3]);
            FMA2(a2[0], xa.x, w2, a2[0]);
            FMA2(a2[1], xa.y, w2, a2[1]);
            FMA2(a2[2], xb.x, w2, a2[2]);
            FMA2(a2[3], xb.y, w2, a2[3]);
        }
        __syncthreads();
    }
}

__global__ __launch_bounds__(256)
void mlp_kernel(const float* __restrict__ Wmlp, const float* __restrict__ bmlp,
                const float* __restrict__ W11, const float* __restrict__ b11,
                const float* __restrict__ W12, const float* __restrict__ b12,
                const float* __restrict__ W1p, const float* __restrict__ b1p,
                const float* __restrict__ W21, const float* __restrict__ b21,
                const float* __restrict__ W22, const float* __restrict__ b22,
                const float* __restrict__ W2p, const float* __restrict__ b2p,
                const float* __restrict__ Wout, const float* __restrict__ bout,
                float* __restrict__ out) {
    extern __shared__ float smem[];
    float* s_f = smem;                 // 128*8 interleaved [i][r]
    float* s_h = smem + 1024;          // 256*8 interleaved
    float* s_q = s_h + 2048;           // 256*8 interleaved
    float* wbuf = s_q + 2048;          // 2*STAGE_F

    int b0 = blockIdx.x * ROWS;
    int j = threadIdx.x;

    // load fused, transposing to interleaved [i][r]
    for (int idx = j; idx < ROWS * 128; idx += 256) {
        int r = idx >> 7, i = idx & 127;
        s_f[i * 8 + r] = g_fused[(long)b0 * 128 + idx];
    }
    __syncthreads();

    // h = relu(fused @ Wmlp + bmlp)
    {
        ull acc[4];
        ull bp = pack2s(bmlp[j]);
#pragma unroll
        for (int p = 0; p < 4; p++) acc[p] = bp;
        gemm_single_p<128, 64>(Wmlp, s_f, wbuf, j, acc);
#pragma unroll
        for (int p = 0; p < 4; p++) {
            float a, b;
            unpack2(acc[p], a, b);
            *(ull*)(s_h + j * 8 + 2 * p) = pack2(fmaxf(a, 0.f), fmaxf(b, 0.f));
        }
    }
    // next gemm's internal first barrier publishes s_h

    const float* Ws1[2] = { W11, W21 };  const float* Bs1[2] = { b11, b21 };
    const float* Ws2[2] = { W12, W22 };  const float* Bs2[2] = { b12, b22 };
    const float* Wsp[2] = { W1p, W2p };  const float* Bsp[2] = { b1p, b2p };

#pragma unroll
    for (int blk = 0; blk < 2; blk++) {
        ull a1[4], a2[4];
        ull bb1 = pack2s(Bs1[blk][j]), bb2 = pack2s(Bs2[blk][j]);
#pragma unroll
        for (int p = 0; p < 4; p++) { a1[p] = bb1; a2[p] = bb2; }
        gemm_dual_p(Ws1[blk], Ws2[blk], s_h, wbuf, j, a1, a2);
#pragma unroll
        for (int p = 0; p < 4; p++) {
            ull qp;
            MUL2(qp, a1[p], a2[p]);
            *(ull*)(s_q + j * 8 + 2 * p) = qp;
        }

        ull ap[4];
        ull bbp = pack2s(Bsp[blk][j]);
#pragma unroll
        for (int p = 0; p < 4; p++) ap[p] = bbp;
        gemm_single_p<256, 64>(Wsp[blk], s_q, wbuf, j, ap);
        // residual: h += proj (each thread owns its own column slice)
#pragma unroll
        for (int p = 0; p < 4; p++) {
            ull hp = *(ull*)(s_h + j * 8 + 2 * p);
            ADD2(hp, hp, ap[p]);
            *(ull*)(s_h + j * 8 + 2 * p) = hp;
        }
    }
    __syncthreads();

    // out[b0+w] = sum_c h[w][c]*Wout[c] + bout  (warp w reduces row w)
    {
        int w = j >> 5, lane = j & 31;
        float v = 0.f;
#pragma unroll
        for (int c = lane; c < HH; c += 32) v += s_h[c * 8 + w] * Wout[c];
#pragma unroll
        for (int off = 16; off; off >>= 1) v += __shfl_down_sync(0xffffffffu, v, off);
        if (lane == 0) out[b0 + w] = v + bout[0];
    }
}

// ---------------------------------------------------------------------------
extern "C" void kernel_launch(void* const* d_in, const int* in_sizes, int n_in,
                              void* d_out, int out_size) {
    const int*   cats    = (const int*)  d_in[0];
    const float* nums    = (const float*)d_in[1];
    const int*   seqs    = (const int*)  d_in[2];
    const int*   tgt_ids = (const int*)  d_in[3];
    const float* cat_emb = (const float*)d_in[4];
    const float* seq_emb = (const float*)d_in[5];
    const float* Wnum    = (const float*)d_in[6];
    const float* bnum    = (const float*)d_in[7];
    const float* Wq      = (const float*)d_in[8];
    const float* Wk      = (const float*)d_in[9];
    const float* Wv      = (const float*)d_in[10];
    const float* Wo      = (const float*)d_in[11];
    const float* bo      = (const float*)d_in[12];
    const float* Wpool   = (const float*)d_in[13];
    const float* bpool   = (const float*)d_in[14];
    const float* Wmlp    = (const float*)d_in[15];
    const float* bmlp    = (const float*)d_in[16];
    const float* q1_W1   = (const float*)d_in[17];
    const float* q1_b1   = (const float*)d_in[18];
    const float* q1_W2   = (const float*)d_in[19];
    const float* q1_b2   = (const float*)d_in[20];
    const float* q1_Wp   = (const float*)d_in[21];
    const float* q1_bp   = (const float*)d_in[22];
    const float* q2_W1   = (const float*)d_in[23];
    const float* q2_b1   = (const float*)d_in[24];
    const float* q2_W2   = (const float*)d_in[25];
    const float* q2_b2   = (const float*)d_in[26];
    const float* q2_Wp   = (const float*)d_in[27];
    const float* q2_bp   = (const float*)d_in[28];
    const float* Wout    = (const float*)d_in[29];
    const float* bout    = (const float*)d_in[30];
    float* out = (float*)d_out;

    cudaFuncSetAttribute(mlp_kernel, cudaFuncAttributeMaxDynamicSharedMemorySize,
                         (1024 + 2048 + 2048 + 2 * STAGE_F) * sizeof(float));

    precompute_kernel<<<2, 256>>>(Wq, Wk, Wv, Wo);
    front_kernel<<<BB, 128>>>(cats, nums, tgt_ids, cat_emb, Wnum, bnum, Wpool, bpool);
    attn_kernel<<<BB, 256>>>(seqs, seq_emb, bo);
    mlp_kernel<<<BB / ROWS, 256, (1024 + 2048 + 2048 + 2 * STAGE_F) * sizeof(float)>>>(
        Wmlp, bmlp,
        q1_W1, q1_b1, q1_W2, q1_b2, q1_Wp, q1_bp,
        q2_W1, q2_b1, q2_W2, q2_b2, q2_Wp, q2_bp,
        Wout, bout, out);
}